// round 8
// baseline (speedup 1.0000x reference)
#include <cuda_runtime.h>
#include <cuda_bf16.h>
#include <cstdint>

// ---------------------------------------------------------------------------
// ImageFusion via mma.sync bf16 GEMMs, hi/lo fp32-split, 3-segment k-loop:
//   A = Ah + Al, B = Bh + Bl;  A@B ~= AhBh + AhBl + AlBh  (AlBl dropped)
// Storage is 2-segment [hi|lo]; the GEMM mainloop walks 3 (segA,segB) pairs.
// N-columns of the QKV weights are permuted so the GEMM epilogue emits the
// exact layout attn reads contiguously; Wo columns permuted so the final
// scatter is 32B-sector coalesced.
// ---------------------------------------------------------------------------

#define Bb    2
#define Hh    256
#define Ww    256
#define Cc    32
#define HEADS 8
#define Mm    2048
#define Kq    2048
#define Ff    16384
#define Kf    16384
#define Nfin  2048

// ---- scratch ----
__device__ __align__(1024) __nv_bfloat16 g_A2[(size_t)Mm * 2 * Kq];       //  16 MB
__device__ __align__(1024) __nv_bfloat16 g_W2[(size_t)3 * Ff * 2 * Kq];   // 402 MB
__device__ __align__(1024) __nv_bfloat16 g_Wo2[(size_t)Nfin * 2 * Kf];    // 134 MB
__device__ float                          g_QKV[(size_t)3 * Mm * Ff];     // 402 MB
__device__ __align__(1024) __nv_bfloat16 g_O2[(size_t)Mm * 2 * Kf];       // 134 MB
__device__ float                          g_bP[3 * Ff + Nfin];            // permuted biases

// ---------------------------------------------------------------------------
// helpers
// ---------------------------------------------------------------------------
static __device__ __forceinline__ uint32_t s2u(const void* p) {
    uint32_t a;
    asm("{ .reg .u64 t; cvta.to.shared.u64 t, %1; cvt.u32.u64 %0, t; }"
        : "=r"(a) : "l"(p));
    return a;
}
static __device__ __forceinline__ void cpa16(uint32_t dst, const void* src) {
    asm volatile("cp.async.cg.shared.global [%0], [%1], 16;\n"
                 :: "r"(dst), "l"(src));
}
static __device__ __forceinline__ void cpa_commit() {
    asm volatile("cp.async.commit_group;\n");
}
template <int N>
static __device__ __forceinline__ void cpa_wait() {
    asm volatile("cp.async.wait_group %0;\n" :: "n"(N));
}
static __device__ __forceinline__ void ldm4(uint32_t* r, uint32_t a) {
    asm volatile("ldmatrix.sync.aligned.m8n8.x4.shared.b16 {%0,%1,%2,%3}, [%4];"
                 : "=r"(r[0]), "=r"(r[1]), "=r"(r[2]), "=r"(r[3]) : "r"(a));
}
static __device__ __forceinline__ void mma16816(float* d, const uint32_t* a,
                                                uint32_t b0, uint32_t b1) {
    asm volatile("mma.sync.aligned.m16n8k16.row.col.f32.bf16.bf16.f32 "
                 "{%0,%1,%2,%3}, {%4,%5,%6,%7}, {%8,%9}, {%0,%1,%2,%3};"
                 : "+f"(d[0]), "+f"(d[1]), "+f"(d[2]), "+f"(d[3])
                 : "r"(a[0]), "r"(a[1]), "r"(a[2]), "r"(a[3]), "r"(b0), "r"(b1));
}

// ---------------------------------------------------------------------------
// GEMM core: BM=128, BN=128, BK=64, 128 threads (4 warps 2x2, warp 64x64),
// 3-stage cp.async pipeline.  SMEM: 16x16 bf16 atoms (512B), atom (ka,i) at
// (ka*8+i)*512; element (row,col) at row*32 + ((col>>3 ^ (row>>2)&1)<<4)
// + (col&7)*2 — conflict-free for both cp.async stores and ldmatrix.
// ---------------------------------------------------------------------------
#define STG_A   16384
#define STG_SZ  32768
#define GSMEM   (3 * STG_SZ)

static __device__ __forceinline__ void load_stage(const __nv_bfloat16* gA,
                                                  const __nv_bfloat16* gB,
                                                  size_t rs, int kA, int kB,
                                                  uint32_t base, int tid) {
#pragma unroll
    for (int it = 0; it < 8; it++) {           // A: 128 rows x 8 16B-chunks
        int q = it * 128 + tid;
        int m = q >> 3, h2 = q & 7;
        uint32_t dst = base + ((h2 >> 1) * 8 + (m >> 4)) * 512 + (m & 15) * 32
                     + (((h2 & 1) ^ ((m >> 2) & 1)) << 4);
        cpa16(dst, gA + (size_t)m * rs + kA + (h2 << 3));
    }
#pragma unroll
    for (int it = 0; it < 8; it++) {           // B: 128 rows x 8 16B-chunks
        int q = it * 128 + tid;
        int n = q >> 3, h2 = q & 7;
        uint32_t dst = base + STG_A + ((h2 >> 1) * 8 + (n >> 4)) * 512
                     + (n & 15) * 32 + (((h2 & 1) ^ ((n >> 2) & 1)) << 4);
        cpa16(dst, gB + (size_t)n * rs + kB + (h2 << 3));
    }
}

static __device__ __forceinline__ void compute_stage(uint32_t sbase, int wm, int wn,
                                                     uint32_t inAtom,
                                                     float acc[4][8][4]) {
    uint32_t abase = sbase + wm * (4 * 512) + inAtom;          // 4 m-atoms/warp
    uint32_t bbase = sbase + STG_A + wn * (4 * 512) + inAtom;  // 4 n-atoms/warp
#pragma unroll
    for (int ks = 0; ks < 4; ks++) {
        uint32_t af[4][4], bf[4][4];
#pragma unroll
        for (int am = 0; am < 4; am++) ldm4(af[am], abase + ks * 4096 + am * 512);
#pragma unroll
        for (int bi = 0; bi < 4; bi++) ldm4(bf[bi], bbase + ks * 4096 + bi * 512);
#pragma unroll
        for (int am = 0; am < 4; am++)
#pragma unroll
            for (int bi = 0; bi < 4; bi++) {
                mma16816(acc[am][bi * 2 + 0], af[am], bf[bi][0], bf[bi][2]);
                mma16816(acc[am][bi * 2 + 1], af[am], bf[bi][1], bf[bi][3]);
            }
    }
}

// 3 segment-pairs: (Ah,Bh), (Ah,Bl), (Al,Bh).  LG = log2(chunks per segment).
template <int LG>
static __device__ __forceinline__ void gemm_mainloop(const __nv_bfloat16* gA,
                                                     const __nv_bfloat16* gB,
                                                     int Kseg, uint32_t sb,
                                                     float acc[4][8][4]) {
    int tid = threadIdx.x, lane = tid & 31, wid = tid >> 5;
    int wm = wid & 1, wn = wid >> 1;
    int quad = lane >> 3;
    int lrow = ((quad & 1) << 3) + (lane & 7);
    int half = quad >> 1;
    uint32_t inAtom = lrow * 32 + ((half ^ ((lrow >> 2) & 1)) << 4);
    size_t rs = 2 * (size_t)Kseg;
    const int niter = 3 << LG, cmask = (1 << LG) - 1;

#pragma unroll
    for (int am = 0; am < 4; am++)
#pragma unroll
        for (int ni = 0; ni < 8; ni++)
#pragma unroll
            for (int j = 0; j < 4; j++) acc[am][ni][j] = 0.f;

    // offsets for iteration i
    auto offs = [&](int i, int& kA, int& kB) {
        int s = i >> LG, w = (i & cmask) << 6;
        kA = (s == 2 ? Kseg : 0) + w;
        kB = (s == 1 ? Kseg : 0) + w;
    };

    { int a, b; offs(0, a, b); load_stage(gA, gB, rs, a, b, sb, tid); }
    cpa_commit();
    { int a, b; offs(1, a, b); load_stage(gA, gB, rs, a, b, sb + STG_SZ, tid); }
    cpa_commit();

    int st = 0, st2 = 2;
    for (int i = 0; i < niter; i++) {
        if (i + 1 < niter) cpa_wait<1>(); else cpa_wait<0>();
        __syncthreads();
        if (i + 2 < niter) {
            int a, b; offs(i + 2, a, b);
            load_stage(gA, gB, rs, a, b, sb + st2 * STG_SZ, tid);
            cpa_commit();
        }
        compute_stage(sb + st * STG_SZ, wm, wn, inAtom, acc);
        st = (st == 2) ? 0 : st + 1;
        st2 = (st2 == 2) ? 0 : st2 + 1;
    }
}

// ---------------------------------------------------------------------------
// K0: transpose + split with column permutation.
//   src fp32 [R][C] -> dst bf16 [C][2R] = [hi | lo], dst row = perm(n).
//   mode 0 (QKV):  n = c*512+p0*64+p1*8+head -> n' = head*2048 + c*64 + pos
//   mode 1 (Wo):   n = c*64+p0*8+p1          -> n' = p0*256 + p1*32 + c
// ---------------------------------------------------------------------------
__global__ void __launch_bounds__(256)
transpose_split_kernel(const float* __restrict__ src,
                       __nv_bfloat16* __restrict__ dst, int R, int C, int mode) {
    __shared__ float t[32][33];
    int tx = threadIdx.x, ty = threadIdx.y;
    int c0 = blockIdx.x * 32, r0 = blockIdx.y * 32;
#pragma unroll
    for (int i = 0; i < 4; i++)
        t[ty + i * 8][tx] = src[(size_t)(r0 + ty + i * 8) * C + c0 + tx];
    __syncthreads();
#pragma unroll
    for (int i = 0; i < 4; i++) {
        float v = t[tx][ty + i * 8];
        int n = c0 + ty + i * 8;
        int np = (mode == 0)
               ? ((n & 7) * 2048 + (n >> 9) * 64 + ((n >> 3) & 63))
               : (((n >> 3) & 7) * 256 + (n & 7) * 32 + (n >> 6));
        size_t base = (size_t)np * (2 * R) + r0 + tx;
        __nv_bfloat16 h = __float2bfloat16(v);
        dst[base]     = h;
        dst[base + R] = __float2bfloat16(v - __bfloat162float(h));
    }
}

// Permute biases into the same column orders.
__global__ void __launch_bounds__(256)
perm_bias_kernel(const float* __restrict__ bq, const float* __restrict__ bk,
                 const float* __restrict__ bv, const float* __restrict__ bo) {
    int i = blockIdx.x * 256 + threadIdx.x;
    if (i < 3 * Ff) {
        int z = i >> 14, f = i & (Ff - 1);
        const float* s = (z == 0) ? bq : ((z == 1) ? bk : bv);
        int fp = (f & 7) * 2048 + (f >> 9) * 64 + ((f >> 3) & 63);
        g_bP[z * Ff + fp] = s[f];
    } else if (i < 3 * Ff + Nfin) {
        int f = i - 3 * Ff;
        int fp = ((f >> 3) & 7) * 256 + (f & 7) * 32 + (f >> 6);
        g_bP[3 * Ff + fp] = bo[f];
    }
}

// ---------------------------------------------------------------------------
// K1: LN over C=32 per pixel + im2col -> A2 [hi | lo].  One warp per pixel.
// ---------------------------------------------------------------------------
__global__ void ln_im2col_kernel(const float* __restrict__ x,
                                 const float* __restrict__ gam,
                                 const float* __restrict__ bet) {
    int pix  = (blockIdx.x * blockDim.x + threadIdx.x) >> 5;
    int lane = threadIdx.x & 31;
    if (pix >= Bb * Hh * Ww) return;

    float v = x[(size_t)pix * Cc + lane];
    float mu = v;
#pragma unroll
    for (int o = 16; o; o >>= 1) mu += __shfl_xor_sync(0xffffffffu, mu, o);
    mu *= (1.0f / 32.0f);
    float d = v - mu;
    float var = d * d;
#pragma unroll
    for (int o = 16; o; o >>= 1) var += __shfl_xor_sync(0xffffffffu, var, o);
    var *= (1.0f / 32.0f);
    float xn = d * rsqrtf(var + 1e-6f) * gam[lane] + bet[lane];

    int w = pix % Ww;
    int h = (pix / Ww) % Hh;
    int b = pix / (Ww * Hh);
    int m = b * 1024 + (h >> 3) * 32 + (w >> 3);
    int k = (h & 7) * 256 + (w & 7) * 32 + lane;
    size_t o = (size_t)m * (2 * Kq) + k;
    __nv_bfloat16 hi = __float2bfloat16(xn);
    g_A2[o]      = hi;
    g_A2[o + Kq] = __float2bfloat16(xn - __bfloat162float(hi));
}

// ---------------------------------------------------------------------------
// K2: Q/K/V GEMM.  grid (16, 128, 3); column-major raster -> B-tile L2 reuse.
// Output columns are permuted: f' = head*2048 + c*64 + pos.
// ---------------------------------------------------------------------------
__global__ void __launch_bounds__(128, 2)
gemm_qkv_kernel() {
    extern __shared__ char smem[];
    uint32_t sb = s2u(smem);
    int tid = threadIdx.x, lane = tid & 31, wid = tid >> 5;
    int wm = wid & 1, wn = wid >> 1;
    int bm = blockIdx.x * 128, bn = blockIdx.y * 128, z = blockIdx.z;

    const __nv_bfloat16* gA = g_A2 + (size_t)bm * (2 * Kq);
    const __nv_bfloat16* gB = g_W2 + ((size_t)z * Ff + bn) * (2 * Kq);

    float acc[4][8][4];
    gemm_mainloop<5>(gA, gB, Kq, sb, acc);

    float* Cg = g_QKV + (size_t)z * Mm * Ff;
    const float* bias = g_bP + z * Ff;
    int g = lane >> 2, t = lane & 3;
#pragma unroll
    for (int am = 0; am < 4; am++)
#pragma unroll
        for (int rr = 0; rr < 2; rr++) {
            int row = bm + wm * 64 + am * 16 + rr * 8 + g;
            float* crow = Cg + (size_t)row * Ff;
#pragma unroll
            for (int ni = 0; ni < 8; ni++) {
                int fp = bn + wn * 64 + ni * 8 + t * 2;
                float2 bi2 = *(const float2*)(bias + fp);
                float2 o;
                o.x = acc[am][ni][rr * 2 + 0] + bi2.x;
                o.y = acc[am][ni][rr * 2 + 1] + bi2.y;
                *(float2*)(crow + fp) = o;
            }
        }
}

// ---------------------------------------------------------------------------
// K3: attention (8x8 circular conv) + LN + gate -> O2 [hi | lo].
// QKV layout is now head-major: Q[m][head*2048 + c*64 + pos] (coalesced).
// ---------------------------------------------------------------------------
__global__ void __launch_bounds__(256)
attn_kernel(const float* __restrict__ l2s, const float* __restrict__ l2b) {
    __shared__ float qs[32 * 64];
    __shared__ float ks[32 * 64];
    __shared__ float vs[32 * 68];
    __shared__ float outs[32 * 68];
    __shared__ float s2[32], b2[32], mus[64], rstds[64];

    int m = blockIdx.x;
    int head = blockIdx.y;
    int tid = threadIdx.x;

    const float* Q  = g_QKV + (size_t)m * Ff + head * 2048;
    const float* Kp = Q + (size_t)Mm * Ff;
    const float* V  = Q + (size_t)2 * Mm * Ff;

    if (tid < 32) { s2[tid] = l2s[tid]; b2[tid] = l2b[tid]; }

#pragma unroll
    for (int it = 0; it < 2; it++) {
        int i4 = it * 256 + tid;                 // float4 index, idx = i4*4
        float4 qv = ((const float4*)Q)[i4];
        float4 kv = ((const float4*)Kp)[i4];
        float4 vv = ((const float4*)V)[i4];
        int idx = i4 * 4;
        *(float4*)&qs[idx] = qv;
        *(float4*)&ks[idx] = kv;
        int c = idx >> 6, pos = idx & 63;
        *(float4*)&vs[c * 68 + pos] = vv;        // 68 = mult of 4, aligned
    }
    __syncthreads();

    float res[8];
#pragma unroll
    for (int j = 0; j < 8; j++) {
        int idx = j * 256 + tid;
        int c = idx >> 6, pos = idx & 63;
        int s = pos >> 3, t = pos & 7;
        const float* qc = &qs[c * 64];
        const float* kc = &ks[c * 64];
        float sum = 0.f;
#pragma unroll
        for (int u = 0; u < 8; u++) {
            int su = ((s - u) & 7) * 8;
#pragma unroll
            for (int v = 0; v < 8; v++)
                sum += qc[u * 8 + v] * kc[su + ((t - v) & 7)];
        }
        res[j] = sum;
    }
#pragma unroll
    for (int j = 0; j < 8; j++) {
        int idx = j * 256 + tid;
        int c = idx >> 6, pos = idx & 63;
        outs[c * 68 + pos] = res[j];
    }
    __syncthreads();

    if (tid < 64) {
        float mu = 0.f;
#pragma unroll
        for (int c = 0; c < 32; c++) mu += outs[c * 68 + tid];
        mu *= (1.0f / 32.0f);
        float var = 0.f;
#pragma unroll
        for (int c = 0; c < 32; c++) {
            float d = outs[c * 68 + tid] - mu;
            var += d * d;
        }
        var *= (1.0f / 32.0f);
        mus[tid] = mu;
        rstds[tid] = rsqrtf(var + 1e-6f);
    }
    __syncthreads();

    size_t Obase = (size_t)m * (2 * Kf);
#pragma unroll
    for (int it = 0; it < 8; it++) {
        int idx = it * 256 + tid;
        int c = idx & 31, pos = idx >> 5;
        int p0 = pos >> 3, p1 = pos & 7;
        float val = (outs[c * 68 + pos] - mus[pos]) * rstds[pos] * s2[c] + b2[c];
        float prod = vs[c * 68 + pos] * val;
        size_t o = Obase + p0 * 2048 + p1 * 256 + head * 32 + c;
        __nv_bfloat16 h = __float2bfloat16(prod);
        g_O2[o]      = h;
        g_O2[o + Kf] = __float2bfloat16(prod - __bfloat162float(h));
    }
}

// ---------------------------------------------------------------------------
// K4: output GEMM + scatter + residual.  grid (16, 16).
// Output columns permuted: f2' = p0*256 + p1*32 + c  -> coalesced scatter.
// ---------------------------------------------------------------------------
__global__ void __launch_bounds__(128, 2)
gemm_out_kernel(const float* __restrict__ xin, float* __restrict__ out) {
    extern __shared__ char smem[];
    uint32_t sb = s2u(smem);
    int tid = threadIdx.x, lane = tid & 31, wid = tid >> 5;
    int wm = wid & 1, wn = wid >> 1;
    int bm = blockIdx.x * 128, bn = blockIdx.y * 128;

    const __nv_bfloat16* gA = g_O2 + (size_t)bm * (2 * Kf);
    const __nv_bfloat16* gB = g_Wo2 + (size_t)bn * (2 * Kf);

    float acc[4][8][4];
    gemm_mainloop<8>(gA, gB, Kf, sb, acc);

    const float* bias = g_bP + 3 * Ff;
    int g = lane >> 2, t = lane & 3;
#pragma unroll
    for (int am = 0; am < 4; am++)
#pragma unroll
        for (int rr = 0; rr < 2; rr++) {
            int row = bm + wm * 64 + am * 16 + rr * 8 + g;
            int b_ = row >> 10, gh = (row >> 5) & 31, gw = row & 31;
#pragma unroll
            for (int ni = 0; ni < 8; ni++) {
                int fp = bn + wn * 64 + ni * 8 + t * 2;
                int c = fp & 31, p1 = (fp >> 5) & 7, p0 = (fp >> 8) & 7;
                size_t oi = (((size_t)(b_ * Hh + gh * 8 + p0)) * Ww
                             + gw * 8 + p1) * Cc + c;
                float2 xi = *(const float2*)(xin + oi);
                float2 bi2 = *(const float2*)(bias + fp);
                float2 o;
                o.x = acc[am][ni][rr * 2 + 0] + bi2.x + xi.x;
                o.y = acc[am][ni][rr * 2 + 1] + bi2.y + xi.y;
                *(float2*)(out + oi) = o;
            }
        }
}

// ---------------------------------------------------------------------------
extern "C" void kernel_launch(void* const* d_in, const int* in_sizes, int n_in,
                              void* d_out, int out_size) {
    const float* x   = (const float*)d_in[0];
    const float* l1s = (const float*)d_in[1];
    const float* l1b = (const float*)d_in[2];
    const float* Wq  = (const float*)d_in[3];
    const float* bq  = (const float*)d_in[4];
    const float* Wk  = (const float*)d_in[5];
    const float* bk  = (const float*)d_in[6];
    const float* Wv  = (const float*)d_in[7];
    const float* bv  = (const float*)d_in[8];
    const float* l2s = (const float*)d_in[9];
    const float* l2b = (const float*)d_in[10];
    const float* Wo  = (const float*)d_in[11];
    const float* bo  = (const float*)d_in[12];
    float* out = (float*)d_out;

    cudaFuncSetAttribute(gemm_qkv_kernel,
                         cudaFuncAttributeMaxDynamicSharedMemorySize, GSMEM);
    cudaFuncSetAttribute(gemm_out_kernel,
                         cudaFuncAttributeMaxDynamicSharedMemorySize, GSMEM);

    void *w2, *wo2;
    cudaGetSymbolAddress(&w2, g_W2);
    cudaGetSymbolAddress(&wo2, g_Wo2);

    dim3 tb(32, 8);
    const size_t WSZ = (size_t)Ff * 2 * Kq;
    transpose_split_kernel<<<dim3(512, 64), tb>>>(Wq, (__nv_bfloat16*)w2, Kq, Ff, 0);
    transpose_split_kernel<<<dim3(512, 64), tb>>>(Wk, (__nv_bfloat16*)w2 + WSZ, Kq, Ff, 0);
    transpose_split_kernel<<<dim3(512, 64), tb>>>(Wv, (__nv_bfloat16*)w2 + 2 * WSZ, Kq, Ff, 0);
    transpose_split_kernel<<<dim3(64, 512), tb>>>(Wo, (__nv_bfloat16*)wo2, Kf, Nfin, 1);

    perm_bias_kernel<<<(3 * Ff + Nfin + 255) / 256, 256>>>(bq, bk, bv, bo);

    ln_im2col_kernel<<<(Bb * Hh * Ww * 32) / 256, 256>>>(x, l1s, l1b);

    dim3 gq(16, 128, 3);
    gemm_qkv_kernel<<<gq, 128, GSMEM>>>();

    dim3 ga(Mm, HEADS);
    attn_kernel<<<ga, 256>>>(l2s, l2b);

    dim3 go(16, 16);
    gemm_out_kernel<<<go, 128, GSMEM>>>(x, out);
}